// round 2
// baseline (speedup 1.0000x reference)
#include <cuda_runtime.h>

// ST-GCN layer, restructured:
//   xwin = 9-tap causal window sum of x (commutes with all channel/joint contractions)
//   y[k=co*3+p, v] = sum_c xwin[c,v] * W[c,k]
//   t[co,w]        = sum_{p,v} y[co*3+p, v] * A[p,v,w]
//   out = relu(relu(BN(t)) + x)
// All fp32, packed f32x2 FMA (V=25 padded to 26).

#define VP 26                 // padded joint dim (pair-friendly)
#define NB 32
#define CI 64
#define LT 300
#define V  25
#define KD 192                // CO*P
#define MT 4                  // time steps per block in main kernel

// scratch: xwin[n][m][c][26]; column 25 is never written -> stays 0 (zero-init global)
__device__ float g_xwin[(size_t)NB * LT * CI * VP];

// ---------- packed f32x2 helpers ----------
__device__ __forceinline__ unsigned long long pack2(float lo, float hi) {
    unsigned long long r;
    asm("mov.b64 %0, {%1,%2};" : "=l"(r) : "f"(lo), "f"(hi));
    return r;
}
__device__ __forceinline__ void unpack2(unsigned long long v, float& lo, float& hi) {
    asm("mov.b64 {%0,%1}, %2;" : "=f"(lo), "=f"(hi) : "l"(v));
}
__device__ __forceinline__ unsigned long long ffma2(unsigned long long a,
                                                    unsigned long long b,
                                                    unsigned long long c) {
    unsigned long long d;
    asm("fma.rn.f32x2 %0, %1, %2, %3;" : "=l"(d) : "l"(a), "l"(b), "l"(c));
    return d;
}

// ---------- kernel 1: sliding window sum ----------
// one block per (n, c); stage the full (L, V) row in smem, 9-tap sum, write padded layout
__global__ __launch_bounds__(256) void win_kernel(const float* __restrict__ x) {
    int n = blockIdx.x >> 6;
    int c = blockIdx.x & 63;
    __shared__ float sx[LT * V];   // 30000 B
    const float* xp = x + ((size_t)(n * CI + c)) * LT * V;
    for (int i = threadIdx.x; i < LT * V; i += 256) sx[i] = xp[i];
    __syncthreads();
    float* ob = g_xwin + ((size_t)n * LT) * CI * VP + (size_t)c * VP;
    for (int i = threadIdx.x; i < LT * V; i += 256) {
        int m = i / V;
        int v = i - m * V;
        float s = 0.f;
        #pragma unroll
        for (int j = 0; j < 9; j++) {
            int l = m - j;
            if (l >= 0) s += sx[l * V + v];
        }
        ob[(size_t)m * CI * VP + v] = s;
    }
}

// ---------- kernel 2: fused contraction + BN + ReLU + residual ----------
// grid = NB * (LT/MT) blocks, 256 threads
// dyn smem: As (3*25*13 ull) | Wsm (64*192) | xw (64*26) | ysm (192*26) | bnA(64) | bnB(64)
#define AS_ULL   (3 * V * 13)
#define SM_FLOAT_BASE (AS_ULL * 2 + 2)          // float index of Wsm, 8B aligned, even
#define SMEM_FLOATS (SM_FLOAT_BASE + CI * KD + CI * VP + KD * VP + 128)
#define SMEM_BYTES  (SMEM_FLOATS * 4)

__global__ __launch_bounds__(256, 2) void main_kernel(
    const float* __restrict__ x,
    const float* __restrict__ A,
    const float* __restrict__ W,
    const float* __restrict__ gamma,
    const float* __restrict__ beta,
    const float* __restrict__ mean,
    const float* __restrict__ var,
    float* __restrict__ out)
{
    extern __shared__ unsigned long long smem_raw[];
    unsigned long long* As = smem_raw;                       // [3][25][13] packed w-pairs
    float* fbase = (float*)smem_raw;
    float* Wsm = fbase + SM_FLOAT_BASE;                      // [64][192]
    float* xw  = Wsm + CI * KD;                              // [64][26]
    float* ysm = xw + CI * VP;                               // [192][26]
    float* bnA = ysm + KD * VP;                              // [64]
    float* bnB = bnA + CI;                                   // [64]

    const int tid = threadIdx.x;
    const int n  = blockIdx.x / (LT / MT);
    const int m0 = (blockIdx.x % (LT / MT)) * MT;

    // block-wide init: BN constants, packed A (w padded), W staged to smem
    for (int i = tid; i < CI; i += 256) {
        float inv = gamma[i] * rsqrtf(var[i] + 1e-3f);
        bnA[i] = inv;
        bnB[i] = beta[i] - mean[i] * inv;
    }
    for (int i = tid; i < AS_ULL; i += 256) {
        int wp = i % 13, pv = i / 13;
        float a0 = A[pv * V + 2 * wp];
        float a1 = (2 * wp + 1 < V) ? A[pv * V + 2 * wp + 1] : 0.f;
        As[i] = pack2(a0, a1);
    }
    for (int i = tid; i < CI * KD; i += 256) Wsm[i] = W[i];

    const int k   = tid;          // phase-1 owner of output row k (<192 active)
    const int wp  = tid & 15;     // phase-2: w-pair (<13 active)
    const int cog = tid >> 4;     // phase-2: co group of 4
    __syncthreads();

    for (int mi = 0; mi < MT; mi++) {
        const int m = m0 + mi;

        // stage xwin tile (64 x 26 floats, contiguous)
        {
            const float4* src = (const float4*)(g_xwin + ((size_t)(n * LT + m)) * CI * VP);
            float4* dst = (float4*)xw;
            for (int i = tid; i < (CI * VP) / 4; i += 256) dst[i] = src[i];
        }
        __syncthreads();

        // phase 1: y[k, :] = sum_c xw[c,:] * W[c,k]   (packed over v-pairs)
        if (k < KD) {
            unsigned long long acc[13];
            #pragma unroll
            for (int vp = 0; vp < 13; vp++) acc[vp] = 0ull;
            #pragma unroll 4
            for (int c = 0; c < CI; c++) {
                float w = Wsm[c * KD + k];
                unsigned long long w2 = pack2(w, w);
                const unsigned long long* xr = (const unsigned long long*)(xw + c * VP);
                #pragma unroll
                for (int vp = 0; vp < 13; vp++) acc[vp] = ffma2(w2, xr[vp], acc[vp]);
            }
            unsigned long long* yr = (unsigned long long*)(ysm + k * VP);
            #pragma unroll
            for (int vp = 0; vp < 13; vp++) yr[vp] = acc[vp];
        }
        __syncthreads();

        // phase 2 + epilogue: t[co, w-pair] = sum_{p,v} y[co*3+p, v] * A[p,v,w-pair]
        if (wp < 13) {
            unsigned long long tacc[4] = {0ull, 0ull, 0ull, 0ull};
            #pragma unroll
            for (int p = 0; p < 3; p++) {
                #pragma unroll 5
                for (int v = 0; v < V; v++) {
                    unsigned long long a2 = As[(p * V + v) * 13 + wp];
                    #pragma unroll
                    for (int i = 0; i < 4; i++) {
                        int kk = (cog * 4 + i) * 3 + p;
                        float yv = ysm[kk * VP + v];
                        tacc[i] = ffma2(pack2(yv, yv), a2, tacc[i]);
                    }
                }
            }
            const int w0 = 2 * wp;
            #pragma unroll
            for (int i = 0; i < 4; i++) {
                int co = cog * 4 + i;
                float t0, t1;
                unpack2(tacc[i], t0, t1);
                float iv = bnA[co], bb = bnB[co];
                size_t base = ((size_t)((n * CI + co) * LT + m)) * V;
                float r0 = fmaxf(fmaf(t0, iv, bb), 0.f);
                out[base + w0] = fmaxf(r0 + x[base + w0], 0.f);
                if (w0 + 1 < V) {
                    float r1 = fmaxf(fmaf(t1, iv, bb), 0.f);
                    out[base + w0 + 1] = fmaxf(r1 + x[base + w0 + 1], 0.f);
                }
            }
        }
        __syncthreads();
    }
}

extern "C" void kernel_launch(void* const* d_in, const int* in_sizes, int n_in,
                              void* d_out, int out_size) {
    const float* x     = (const float*)d_in[0];
    const float* A     = (const float*)d_in[1];
    const float* W     = (const float*)d_in[2];
    const float* gamma = (const float*)d_in[3];
    const float* beta  = (const float*)d_in[4];
    const float* mean  = (const float*)d_in[5];
    const float* var   = (const float*)d_in[6];
    float* out = (float*)d_out;

    win_kernel<<<NB * CI, 256>>>(x);

    cudaFuncSetAttribute(main_kernel, cudaFuncAttributeMaxDynamicSharedMemorySize, SMEM_BYTES);
    main_kernel<<<NB * (LT / MT), 256, SMEM_BYTES>>>(x, A, W, gamma, beta, mean, var, out);
}

// round 3
// speedup vs baseline: 1.8532x; 1.8532x over previous
#include <cuda_runtime.h>

#define NB 32
#define CI 64
#define LT 300
#define V  25
#define VP 26
#define KD 192

typedef unsigned long long ull;

// scratch: xwin[n][m][c][26]; v=25 column written as 0 explicitly
__device__ float g_xwin[(size_t)NB * LT * CI * VP];

__device__ __forceinline__ ull pack2(float lo, float hi){
    ull r; asm("mov.b64 %0,{%1,%2};" : "=l"(r) : "f"(lo), "f"(hi)); return r;
}
__device__ __forceinline__ void unpack2(ull v, float& lo, float& hi){
    asm("mov.b64 {%0,%1},%2;" : "=f"(lo), "=f"(hi) : "l"(v));
}
__device__ __forceinline__ ull ffma2(ull a, ull b, ull c){
    ull d; asm("fma.rn.f32x2 %0,%1,%2,%3;" : "=l"(d) : "l"(a), "l"(b), "l"(c)); return d;
}

// ---------- kernel 1: sliding 9-tap window sum ----------
// block = (n, m-tile of 12, c-half of 32): contiguous reads AND contiguous writes
#define WMT 12
#define WLL 20            // WMT + 8 halo
#define WCH 32
#define WIN_SMEM (WCH * WLL * V * 4)   // 64000 B

__global__ __launch_bounds__(256) void win_kernel(const float* __restrict__ x){
    extern __shared__ float sx[];       // [WCH][WLL][V]
    int b  = blockIdx.x;
    int n  = b / ((LT/WMT)*2);
    int r  = b % ((LT/WMT)*2);
    int m0 = (r >> 1) * WMT;
    int c0 = (r & 1) * WCH;

    for (int idx = threadIdx.x; idx < WCH*WLL*V; idx += 256){
        int c   = idx / (WLL*V);
        int rem = idx - c*(WLL*V);
        int ls  = rem / V;
        int v   = rem - ls*V;
        int l   = m0 - 8 + ls;
        sx[idx] = (l >= 0) ? x[((size_t)(n*CI + c0 + c)*LT + l)*V + v] : 0.f;
    }
    __syncthreads();

    float* ob = g_xwin + ((size_t)(n*LT + m0)*CI + c0)*VP;
    for (int idx = threadIdx.x; idx < WMT*WCH*VP; idx += 256){
        int mi  = idx / (WCH*VP);
        int rem = idx - mi*(WCH*VP);
        int c   = rem / VP;
        int v   = rem - c*VP;
        float s = 0.f;
        if (v < V){
            #pragma unroll
            for (int j = 0; j < 9; j++) s += sx[(c*WLL + (mi + 8 - j))*V + v];
        }
        ob[(size_t)mi*CI*VP + c*VP + v] = s;
    }
}

// ---------- kernel 2: fused contraction + BN + ReLU + residual ----------
// blockDim 192, one block per (n, pair of m). Register-blocked both phases.
#define TPB 192
#define MAIN_SMEM (75*16*8 + 2*CI*VP*4 + 2*KD*VP*4 + 2*CI*4)   // 63360 B

__global__ __launch_bounds__(TPB, 3) void main_kernel(
    const float* __restrict__ x,
    const float* __restrict__ A,
    const float* __restrict__ W,
    const float* __restrict__ gamma,
    const float* __restrict__ beta,
    const float* __restrict__ mean,
    const float* __restrict__ var,
    float* __restrict__ out)
{
    extern __shared__ ull smem[];
    ull*   As  = smem;                       // [75][16] packed w-pairs (pairs 13..15 zero)
    float* xwf = (float*)(As + 75*16);       // [2][64][26]
    float* ysm = xwf + 2*CI*VP;              // [2][192][26]
    float* bnA = ysm + 2*KD*VP;              // [64]
    float* bnB = bnA + CI;                   // [64]

    const int tid = threadIdx.x;
    const int n   = blockIdx.x / (LT/2);
    const int m0  = (blockIdx.x % (LT/2)) * 2;

    // ---- init: BN constants + padded packed A + xwin tile staging ----
    if (tid < CI){
        float inv = gamma[tid] * rsqrtf(var[tid] + 1e-3f);
        bnA[tid] = inv;
        bnB[tid] = beta[tid] - mean[tid]*inv;
    }
    for (int i = tid; i < 75*16; i += TPB){
        int pv = i >> 4;
        int wp = i & 15;
        ull val = 0;
        if (wp < 13){
            float a0 = A[pv*V + 2*wp];
            float a1 = (wp < 12) ? A[pv*V + 2*wp + 1] : 0.f;
            val = pack2(a0, a1);
        }
        As[i] = val;
    }
    {
        const float4* src = (const float4*)(g_xwin + (size_t)(n*LT + m0)*CI*VP);
        float4* dst = (float4*)xwf;
        for (int i = tid; i < (2*CI*VP)/4; i += TPB) dst[i] = src[i];
    }
    __syncthreads();

    // ---- phase 1: y[k,:] = sum_c xw[c,:] * W[c,k], 2 k-rows per thread ----
    {
        const int mslot = tid / 96;
        const int s     = tid - mslot*96;
        const int k0    = 2*s;
        const ull* xr = (const ull*)(xwf + mslot*CI*VP);
        ull accL[13], accH[13];
        #pragma unroll
        for (int vp = 0; vp < 13; vp++){ accL[vp] = 0; accH[vp] = 0; }

        float2 wv = __ldg((const float2*)(W + k0));
        #pragma unroll 4
        for (int c = 0; c < CI; c++){
            float2 wn = (c < CI-1) ? __ldg((const float2*)(W + (c+1)*KD + k0))
                                   : make_float2(0.f, 0.f);
            ull wL = pack2(wv.x, wv.x);
            ull wH = pack2(wv.y, wv.y);
            const ull* xc = xr + c*13;
            #pragma unroll
            for (int vp = 0; vp < 13; vp++){
                ull xv = xc[vp];
                accL[vp] = ffma2(wL, xv, accL[vp]);
                accH[vp] = ffma2(wH, xv, accH[vp]);
            }
            wv = wn;
        }
        ull* y0 = (ull*)(ysm + (size_t)(mslot*KD + k0    )*VP);
        ull* y1 = (ull*)(ysm + (size_t)(mslot*KD + k0 + 1)*VP);
        #pragma unroll
        for (int vp = 0; vp < 13; vp++){ y0[vp] = accL[vp]; y1[vp] = accH[vp]; }
    }
    __syncthreads();

    // ---- phase 2: t[co,w] = sum_{p,v} y[co*3+p,v] * A[p,v,w], 4co x 4wpairs tile ----
    if (tid < 128){
        const int mslot = tid >> 6;
        const int s2    = tid & 63;
        const int cog   = s2 >> 2;     // 16 groups of 4 co
        const int wg    = s2 & 3;      // pair-group: pairs wg*4 .. wg*4+3
        const int co0   = cog * 4;

        ull tac[4][4];
        #pragma unroll
        for (int i = 0; i < 4; i++)
            #pragma unroll
            for (int j = 0; j < 4; j++) tac[i][j] = 0;

        const float* yb = ysm + (size_t)mslot*KD*VP;
        #pragma unroll
        for (int p = 0; p < 3; p++){
            const ull* Ab = As + (p*V)*16 + wg*4;
            const float* yp = yb + (size_t)(co0*3 + p)*VP;
            #pragma unroll 5
            for (int v = 0; v < V; v++){
                ull a0 = Ab[v*16+0], a1 = Ab[v*16+1], a2 = Ab[v*16+2], a3 = Ab[v*16+3];
                #pragma unroll
                for (int i = 0; i < 4; i++){
                    float yv = yp[i*3*VP + v];
                    ull yy = pack2(yv, yv);
                    tac[i][0] = ffma2(yy, a0, tac[i][0]);
                    tac[i][1] = ffma2(yy, a1, tac[i][1]);
                    tac[i][2] = ffma2(yy, a2, tac[i][2]);
                    tac[i][3] = ffma2(yy, a3, tac[i][3]);
                }
            }
        }

        // epilogue: BN + ReLU + residual + ReLU
        const int m = m0 + mslot;
        #pragma unroll
        for (int i = 0; i < 4; i++){
            int co = co0 + i;
            float iv = bnA[co], bb = bnB[co];
            size_t base = ((size_t)(n*CI + co)*LT + m)*V;
            #pragma unroll
            for (int j = 0; j < 4; j++){
                int w0 = 2*(wg*4 + j);
                if (w0 >= V) break;          // wg==3: only pair 12 (w=24) is real
                float t0, t1; unpack2(tac[i][j], t0, t1);
                float r0 = fmaxf(fmaf(t0, iv, bb), 0.f);
                out[base + w0] = fmaxf(r0 + x[base + w0], 0.f);
                if (w0 + 1 < V){
                    float r1 = fmaxf(fmaf(t1, iv, bb), 0.f);
                    out[base + w0 + 1] = fmaxf(r1 + x[base + w0 + 1], 0.f);
                }
            }
        }
    }
}

extern "C" void kernel_launch(void* const* d_in, const int* in_sizes, int n_in,
                              void* d_out, int out_size) {
    const float* x     = (const float*)d_in[0];
    const float* A     = (const float*)d_in[1];
    const float* W     = (const float*)d_in[2];
    const float* gamma = (const float*)d_in[3];
    const float* beta  = (const float*)d_in[4];
    const float* mean  = (const float*)d_in[5];
    const float* var   = (const float*)d_in[6];
    float* out = (float*)d_out;

    cudaFuncSetAttribute(win_kernel, cudaFuncAttributeMaxDynamicSharedMemorySize, WIN_SMEM);
    win_kernel<<<NB * (LT/WMT) * 2, 256, WIN_SMEM>>>(x);

    cudaFuncSetAttribute(main_kernel, cudaFuncAttributeMaxDynamicSharedMemorySize, MAIN_SMEM);
    main_kernel<<<NB * (LT/2), TPB, MAIN_SMEM>>>(x, A, W, gamma, beta, mean, var, out);
}

// round 4
// speedup vs baseline: 2.1956x; 1.1848x over previous
#include <cuda_runtime.h>

#define NB 32
#define CI 64
#define LT 300
#define V  25
#define VP 26
#define KD 192

typedef unsigned long long ull;

// scratch: xwin[n][m][c][26]; v=25 pad column never written -> stays 0 (zero-init)
__device__ float g_xwin[(size_t)NB * LT * CI * VP];

__device__ __forceinline__ ull pack2(float lo, float hi){
    ull r; asm("mov.b64 %0,{%1,%2};" : "=l"(r) : "f"(lo), "f"(hi)); return r;
}
__device__ __forceinline__ void unpack2(ull v, float& lo, float& hi){
    asm("mov.b64 {%0,%1},%2;" : "=f"(lo), "=f"(hi) : "l"(v));
}
__device__ __forceinline__ ull ffma2(ull a, ull b, ull c){
    ull d; asm("fma.rn.f32x2 %0,%1,%2,%3;" : "=l"(d) : "l"(a), "l"(b), "l"(c)); return d;
}

// ---------- kernel 1: 9-tap causal window sum, register running-sum stream ----------
// block = (n, c-group of 8, l-quarter of 75); thread = (c_local, v)
// per output: 1 coalesced LDG + 2 FADD + 1 coalesced STG, no smem
#define WCG 8      // channels per block
#define WLQ 75     // l per quarter
#define WTH (WCG * V)   // 200 threads

__global__ __launch_bounds__(WTH) void win_kernel(const float* __restrict__ x){
    const int b  = blockIdx.x;
    const int q  = b & 3;
    const int cg = (b >> 2) & 7;
    const int n  = b >> 5;
    const int t  = threadIdx.x;
    const int cl = t / V;
    const int v  = t - cl * V;
    const int c  = cg * WCG + cl;
    const int l0 = q * WLQ;

    const float* xp = x + ((size_t)(n * CI + c) * LT) * V + v;
    float* op = g_xwin + ((size_t)n * LT * CI + c) * VP + v;

    float ring[9];
    #pragma unroll
    for (int j = 0; j < 9; j++) ring[j] = 0.f;
    float s = 0.f;

    // cover l0-8 .. l0+81 in 10 chunks of 9; stores gated to [l0, l0+75)
    #pragma unroll 1
    for (int base = 0; base < 90; base += 9) {
        #pragma unroll
        for (int j = 0; j < 9; j++) {
            int l = l0 - 8 + base + j;
            float nv = (l >= 0 && l < LT) ? xp[(size_t)l * V] : 0.f;
            s += nv - ring[j];
            ring[j] = nv;
            if (l >= l0 && l < l0 + WLQ)
                op[(size_t)l * CI * VP] = s;
        }
    }
}

// ---------- kernel 2: fused contraction + BN + ReLU + residual ----------
#define TPB 192
#define MAIN_SMEM (75*16*8 + 2*CI*VP*4 + 2*KD*VP*4 + 2*CI*4)   // 63360 B

__global__ __launch_bounds__(TPB, 3) void main_kernel(
    const float* __restrict__ x,
    const float* __restrict__ A,
    const float* __restrict__ W,
    const float* __restrict__ gamma,
    const float* __restrict__ beta,
    const float* __restrict__ mean,
    const float* __restrict__ var,
    float* __restrict__ out)
{
    extern __shared__ ull smem[];
    ull*   As  = smem;                       // [75][16] packed w-pairs (13..15 zero)
    float* xwf = (float*)(As + 75*16);       // [2][64][26]
    float* ysm = xwf + 2*CI*VP;              // [2][192][26]
    float* bnA = ysm + 2*KD*VP;              // [64]
    float* bnB = bnA + CI;                   // [64]

    const int tid = threadIdx.x;
    const int n   = blockIdx.x / (LT/2);
    const int m0  = (blockIdx.x % (LT/2)) * 2;

    if (tid < CI){
        float inv = gamma[tid] * rsqrtf(var[tid] + 1e-3f);
        bnA[tid] = inv;
        bnB[tid] = beta[tid] - mean[tid]*inv;
    }
    for (int i = tid; i < 75*16; i += TPB){
        int pv = i >> 4, wp = i & 15;
        ull val = 0;
        if (wp < 13){
            float a0 = A[pv*V + 2*wp];
            float a1 = (wp < 12) ? A[pv*V + 2*wp + 1] : 0.f;
            val = pack2(a0, a1);
        }
        As[i] = val;
    }
    {
        const float4* src = (const float4*)(g_xwin + (size_t)(n*LT + m0)*CI*VP);
        float4* dst = (float4*)xwf;
        for (int i = tid; i < (2*CI*VP)/4; i += TPB) dst[i] = src[i];
    }
    __syncthreads();

    // ---- phase 1: y[k,:] = sum_c xw[c,:]*W[c,k]; 4 k-rows x 7 v-pairs per thread ----
    // v-halves: vh0 -> pairs 0..6, vh1 -> pairs 6..12 (pair 6 duplicated, identical)
    {
        const int mslot = tid / 96;
        const int s     = tid - mslot*96;
        const int kg    = s >> 1;
        const int vh    = s & 1;
        const int k0    = kg * 4;
        const int voff  = vh * 6;
        const ull* xr = (const ull*)(xwf + mslot*CI*VP);

        ull acc[4][7];
        #pragma unroll
        for (int i = 0; i < 4; i++)
            #pragma unroll
            for (int vp = 0; vp < 7; vp++) acc[i][vp] = 0;

        #pragma unroll 2
        for (int c = 0; c < CI; c++){
            float4 w = __ldg((const float4*)(W + c*KD + k0));
            ull w0 = pack2(w.x, w.x), w1 = pack2(w.y, w.y);
            ull w2 = pack2(w.z, w.z), w3 = pack2(w.w, w.w);
            const ull* xc = xr + c*13 + voff;
            #pragma unroll
            for (int vp = 0; vp < 7; vp++){
                ull xv = xc[vp];
                acc[0][vp] = ffma2(w0, xv, acc[0][vp]);
                acc[1][vp] = ffma2(w1, xv, acc[1][vp]);
                acc[2][vp] = ffma2(w2, xv, acc[2][vp]);
                acc[3][vp] = ffma2(w3, xv, acc[3][vp]);
            }
        }
        #pragma unroll
        for (int i = 0; i < 4; i++){
            ull* yr = (ull*)(ysm) + (size_t)(mslot*KD + k0 + i)*13 + voff;
            #pragma unroll
            for (int vp = 0; vp < 7; vp++) yr[vp] = acc[i][vp];
        }
    }
    __syncthreads();

    // ---- phase 2: t[co,w] = sum_{p,v} y[co*3+p,v]*A[p,v,w]; 4co x 4wpairs, v paired ----
    if (tid < 128){
        const int mslot = tid >> 6;
        const int s2    = tid & 63;
        const int cog   = s2 >> 2;
        const int wg    = s2 & 3;
        const int co0   = cog * 4;

        ull tac[4][4];
        #pragma unroll
        for (int i = 0; i < 4; i++)
            #pragma unroll
            for (int j = 0; j < 4; j++) tac[i][j] = 0;

        const float* yb = ysm + (size_t)mslot*KD*VP;
        #pragma unroll
        for (int p = 0; p < 3; p++){
            const ull* Ab = As + (p*V)*16 + wg*4;
            const float* yp = yb + (size_t)(co0*3 + p)*VP;
            #pragma unroll 3
            for (int v2 = 0; v2 < 12; v2++){
                int v = 2*v2;
                ull a00 = Ab[(v  )*16+0], a01 = Ab[(v  )*16+1], a02 = Ab[(v  )*16+2], a03 = Ab[(v  )*16+3];
                ull a10 = Ab[(v+1)*16+0], a11 = Ab[(v+1)*16+1], a12 = Ab[(v+1)*16+2], a13 = Ab[(v+1)*16+3];
                #pragma unroll
                for (int i = 0; i < 4; i++){
                    float y0, y1;
                    unpack2(*(const ull*)(yp + i*3*VP + v), y0, y1);
                    ull yy0 = pack2(y0, y0), yy1 = pack2(y1, y1);
                    tac[i][0] = ffma2(yy0, a00, tac[i][0]);
                    tac[i][1] = ffma2(yy0, a01, tac[i][1]);
                    tac[i][2] = ffma2(yy0, a02, tac[i][2]);
                    tac[i][3] = ffma2(yy0, a03, tac[i][3]);
                    tac[i][0] = ffma2(yy1, a10, tac[i][0]);
                    tac[i][1] = ffma2(yy1, a11, tac[i][1]);
                    tac[i][2] = ffma2(yy1, a12, tac[i][2]);
                    tac[i][3] = ffma2(yy1, a13, tac[i][3]);
                }
            }
            { // leftover v = 24
                ull a0 = Ab[24*16+0], a1 = Ab[24*16+1], a2 = Ab[24*16+2], a3 = Ab[24*16+3];
                #pragma unroll
                for (int i = 0; i < 4; i++){
                    float yv = yp[i*3*VP + 24];
                    ull yy = pack2(yv, yv);
                    tac[i][0] = ffma2(yy, a0, tac[i][0]);
                    tac[i][1] = ffma2(yy, a1, tac[i][1]);
                    tac[i][2] = ffma2(yy, a2, tac[i][2]);
                    tac[i][3] = ffma2(yy, a3, tac[i][3]);
                }
            }
        }

        const int m = m0 + mslot;
        #pragma unroll
        for (int i = 0; i < 4; i++){
            int co = co0 + i;
            float iv = bnA[co], bb = bnB[co];
            size_t base = ((size_t)(n*CI + co)*LT + m)*V;
            #pragma unroll
            for (int j = 0; j < 4; j++){
                int w0 = 2*(wg*4 + j);
                if (w0 >= V) break;
                float t0, t1; unpack2(tac[i][j], t0, t1);
                float r0 = fmaxf(fmaf(t0, iv, bb), 0.f);
                out[base + w0] = fmaxf(r0 + x[base + w0], 0.f);
                if (w0 + 1 < V){
                    float r1 = fmaxf(fmaf(t1, iv, bb), 0.f);
                    out[base + w0 + 1] = fmaxf(r1 + x[base + w0 + 1], 0.f);
                }
            }
        }
    }
}

extern "C" void kernel_launch(void* const* d_in, const int* in_sizes, int n_in,
                              void* d_out, int out_size) {
    const float* x     = (const float*)d_in[0];
    const float* A     = (const float*)d_in[1];
    const float* W     = (const float*)d_in[2];
    const float* gamma = (const float*)d_in[3];
    const float* beta  = (const float*)d_in[4];
    const float* mean  = (const float*)d_in[5];
    const float* var   = (const float*)d_in[6];
    float* out = (float*)d_out;

    win_kernel<<<NB * 8 * 4, WTH>>>(x);

    cudaFuncSetAttribute(main_kernel, cudaFuncAttributeMaxDynamicSharedMemorySize, MAIN_SMEM);
    main_kernel<<<NB * (LT/2), TPB, MAIN_SMEM>>>(x, A, W, gamma, beta, mean, var, out);
}